// round 9
// baseline (speedup 1.0000x reference)
#include <cuda_runtime.h>
#include <cuda_fp16.h>
#include <math.h>
#include <stdint.h>

#define B_      8
#define C_      192
#define C3      576
#define HW      16384
#define HEADS_  4
#define HC      48
#define NCHUNK  128
#define GCHUNKS 32
#define NPART   128
#define PART_STRIDE 2400

// -------- device scratch --------
__device__ __half g_qkv [(size_t)B_ * C3 * HW];
__device__ __half g_dwq [(size_t)B_ * C3 * HW];
__device__ float  g_part[(size_t)NPART * 32 * PART_STRIDE];
__device__ float  g_gram[32 * HC * HC];
__device__ float  g_nq  [32 * HC];
__device__ float  g_nk  [32 * HC];
__device__ float  g_attn[32 * HC * HC];
__device__ float  g_weff[B_ * C_ * C_];

// ============================================================
__device__ __forceinline__ void mma_f16(float* d, const uint32_t* a,
                                        uint32_t b0, uint32_t b1) {
    asm volatile(
        "mma.sync.aligned.m16n8k16.row.col.f32.f16.f16.f32 "
        "{%0,%1,%2,%3}, {%4,%5,%6,%7}, {%8,%9}, {%0,%1,%2,%3};\n"
        : "+f"(d[0]), "+f"(d[1]), "+f"(d[2]), "+f"(d[3])
        : "r"(a[0]), "r"(a[1]), "r"(a[2]), "r"(a[3]),
          "r"(b0), "r"(b1));
}

// ============================================================
// Tensor-core GEMM: C[b] = A[b](MxK fp32) @ B[b](KxN), N=HW, K=192.
// BM=96 BN=128 BK=32. 128 threads / 4 warps (2M x 2N), warp tile 48x64.
// A (96x192) preloaded to smem ONCE (no per-iter A traffic).
// B double-buffered, 6 iterations.
// ============================================================
#define BM 96
#define BN 128
#define BK 32
#define ASX 104   // A stride in half2 (96+8): 104 % 32 == 8 -> conflict-free
#define BSX 136   // B stride in half2 (128+8)
#define SMEM_G (96 * ASX * 4 + 2 * 16 * BSX * 4)   // 39936 + 17408 = 57344

template <bool B_HALF, bool OUT_HALF>
__global__ __launch_bounds__(128) void gemm_f16(
    const float* __restrict__ A, const void* __restrict__ Bv,
    void* __restrict__ Cv, int K,
    size_t sAb, size_t sBb, size_t sCb)
{
    extern __shared__ char smem[];
    __half2 (*Aall)[ASX] = (__half2 (*)[ASX])smem;                 // [96 k2][m]
    __half2 (*Bsh)[16][BSX] = (__half2 (*)[16][BSX])(smem + 96 * ASX * 4);

    const int N = HW;
    A += (size_t)blockIdx.z * sAb;
    const int m0 = blockIdx.x * BM;
    const int n0 = blockIdx.y * BN;

    const int tid  = threadIdx.x;
    const int warp = tid >> 5;
    const int lane = tid & 31;
    const int wm = (warp & 1) * 48;
    const int wn = (warp >> 1) * 64;
    const int grp = lane >> 2;
    const int qd  = lane & 3;

    // ---- A preload: 96 rows x 192 k, fp32 -> fp16 k-pair layout ----
    for (int idx = tid; idx < 96 * 48; idx += 128) {
        const int row = idx / 48;
        const int kq  = (idx % 48) * 4;
        float4 v = *(const float4*)&A[(size_t)(m0 + row) * K + kq];
        Aall[(kq >> 1)    ][row] = __float22half2_rn(make_float2(v.x, v.y));
        Aall[(kq >> 1) + 1][row] = __float22half2_rn(make_float2(v.z, v.w));
    }

    // B loader: each thread owns 2 k-rows (2*bk2L, 2*bk2L+1) x 16 n-cols
    const int bk2L = tid >> 3;           // 0..15
    const int bnc  = (tid & 7) << 4;     // 0..112

    const float*  Bf = (const float*)Bv + (size_t)blockIdx.z * sBb;
    const __half* Bh = (const __half*)Bv + (size_t)blockIdx.z * sBb;

    float4 bRegF[8];
    uint4  bRegH[4];

    auto loadG = [&](int k0) {
        const int r0 = k0 + 2 * bk2L;
        if (B_HALF) {
            bRegH[0] = *(const uint4*)&Bh[(size_t)r0 * N + n0 + bnc];
            bRegH[1] = *(const uint4*)&Bh[(size_t)r0 * N + n0 + bnc + 8];
            bRegH[2] = *(const uint4*)&Bh[(size_t)(r0 + 1) * N + n0 + bnc];
            bRegH[3] = *(const uint4*)&Bh[(size_t)(r0 + 1) * N + n0 + bnc + 8];
        } else {
#pragma unroll
            for (int j = 0; j < 4; j++)
                bRegF[j]     = *(const float4*)&Bf[(size_t)r0 * N + n0 + bnc + j * 4];
#pragma unroll
            for (int j = 0; j < 4; j++)
                bRegF[4 + j] = *(const float4*)&Bf[(size_t)(r0 + 1) * N + n0 + bnc + j * 4];
        }
    };

    auto storeS = [&](int buf) {
        __half2 h[16];
        if (B_HALF) {
            const __half* r0 = (const __half*)&bRegH[0];
            const __half* r1 = (const __half*)&bRegH[2];
#pragma unroll
            for (int j = 0; j < 16; j++) h[j] = __halves2half2(r0[j], r1[j]);
        } else {
            const float* r0 = (const float*)&bRegF[0];
            const float* r1 = (const float*)&bRegF[4];
#pragma unroll
            for (int j = 0; j < 16; j++)
                h[j] = __float22half2_rn(make_float2(r0[j], r1[j]));
        }
#pragma unroll
        for (int j = 0; j < 4; j++)
            *(uint4*)&Bsh[buf][bk2L][bnc + j * 4] = *(uint4*)&h[j * 4];
    };

    float acc[3][8][4];
#pragma unroll
    for (int i = 0; i < 3; i++)
#pragma unroll
        for (int j = 0; j < 8; j++)
#pragma unroll
            for (int r = 0; r < 4; r++) acc[i][j][r] = 0.f;

    const int NK = K / BK;   // 6

    loadG(0);
    storeS(0);
    __syncthreads();

    for (int it = 0; it < NK; it++) {
        const int cur = it & 1;
        if (it + 1 < NK) loadG((it + 1) * BK);

#pragma unroll
        for (int ks = 0; ks < 2; ks++) {
            const int k2g = it * 16 + ks * 8;   // global k2 for A
            const int k2l = ks * 8;             // local k2 for B
            uint32_t af[3][4];
#pragma unroll
            for (int mt = 0; mt < 3; mt++) {
                const int m = wm + mt * 16 + grp;
                af[mt][0] = *(const uint32_t*)&Aall[k2g + qd    ][m];
                af[mt][1] = *(const uint32_t*)&Aall[k2g + qd    ][m + 8];
                af[mt][2] = *(const uint32_t*)&Aall[k2g + qd + 4][m];
                af[mt][3] = *(const uint32_t*)&Aall[k2g + qd + 4][m + 8];
            }
#pragma unroll
            for (int nt = 0; nt < 8; nt++) {
                const int n = wn + nt * 8 + grp;
                const uint32_t b0 = *(const uint32_t*)&Bsh[cur][k2l + qd    ][n];
                const uint32_t b1 = *(const uint32_t*)&Bsh[cur][k2l + qd + 4][n];
#pragma unroll
                for (int mt = 0; mt < 3; mt++)
                    mma_f16(acc[mt][nt], af[mt], b0, b1);
            }
        }

        if (it + 1 < NK) {
            storeS((it + 1) & 1);
            __syncthreads();
        }
    }

    if (OUT_HALF) {
        __half* Ch = (__half*)Cv + (size_t)blockIdx.z * sCb;
#pragma unroll
        for (int mt = 0; mt < 3; mt++) {
#pragma unroll
            for (int nt = 0; nt < 8; nt++) {
                const int row = m0 + wm + mt * 16 + grp;
                const int col = n0 + wn + nt * 8 + qd * 2;
                *(__half2*)&Ch[(size_t)row * N + col] =
                    __float22half2_rn(make_float2(acc[mt][nt][0], acc[mt][nt][1]));
                *(__half2*)&Ch[(size_t)(row + 8) * N + col] =
                    __float22half2_rn(make_float2(acc[mt][nt][2], acc[mt][nt][3]));
            }
        }
    } else {
        float* Cf = (float*)Cv + (size_t)blockIdx.z * sCb;
#pragma unroll
        for (int mt = 0; mt < 3; mt++) {
#pragma unroll
            for (int nt = 0; nt < 8; nt++) {
                const int row = m0 + wm + mt * 16 + grp;
                const int col = n0 + wn + nt * 8 + qd * 2;
                *(float2*)&Cf[(size_t)row * N + col]       = make_float2(acc[mt][nt][0], acc[mt][nt][1]);
                *(float2*)&Cf[(size_t)(row + 8) * N + col] = make_float2(acc[mt][nt][2], acc[mt][nt][3]);
            }
        }
    }
}

// ============================================================
__global__ void noop_kernel() {}

// ============================================================
// Depthwise 3x3 SAME on fp16 in/out, fp32 compute.
// ============================================================
__global__ __launch_bounds__(256) void dwconv_kernel(const float* __restrict__ wdw)
{
    __shared__ float s[66][130];

    const int half_ = blockIdx.x;
    const int ch    = blockIdx.y;
    const int b     = blockIdx.z;
    const int r0    = half_ * 64;

    const __half* in = g_qkv + ((size_t)b * C3 + ch) * HW;
    __half* outp = g_dwq + ((size_t)b * C3 + ch) * HW;
    const int tid = threadIdx.x;

    for (int r = tid; r < 66; r += 256) { s[r][0] = 0.f; s[r][129] = 0.f; }

    for (int i = tid; i < 66 * 16; i += 256) {
        const int sr = i >> 4;
        const int c8 = (i & 15) << 3;
        const int gr = r0 - 1 + sr;
        if (gr >= 0 && gr < 128) {
            uint4 v = *(const uint4*)&in[gr * 128 + c8];
            const __half2* hp = (const __half2*)&v;
#pragma unroll
            for (int j = 0; j < 4; j++) {
                float2 f = __half22float2(hp[j]);
                s[sr][1 + c8 + 2 * j]     = f.x;
                s[sr][1 + c8 + 2 * j + 1] = f.y;
            }
        } else {
#pragma unroll
            for (int j = 0; j < 8; j++) s[sr][1 + c8 + j] = 0.f;
        }
    }
    __syncthreads();

    float w[9];
#pragma unroll
    for (int i = 0; i < 9; i++) w[i] = __ldg(&wdw[ch * 9 + i]);

    const int lane = tid & 31;
    const int rb   = tid >> 5;

#pragma unroll
    for (int seg = 0; seg < 4; seg++) {
        const int c = lane + seg * 32;
        float o[8];
#pragma unroll
        for (int rr = 0; rr < 10; rr++) {
            const int sr = rb * 8 + rr;
            const float v0 = s[sr][c];
            const float v1 = s[sr][c + 1];
            const float v2 = s[sr][c + 2];
            const float d0 = w[0] * v0 + w[1] * v1 + w[2] * v2;
            const float d1 = w[3] * v0 + w[4] * v1 + w[5] * v2;
            const float d2 = w[6] * v0 + w[7] * v1 + w[8] * v2;
            if (rr < 8)             o[rr]     = d0;
            if (rr >= 1 && rr <= 8) o[rr - 1] += d1;
            if (rr >= 2)            o[rr - 2] += d2;
        }
#pragma unroll
        for (int y = 0; y < 8; y++)
            outp[(r0 + rb * 8 + y) * 128 + c] = __float2half_rn(o[y]);
    }
}

// ============================================================
// Partial Gram (48x48) + q/k norm partials (fp16 input, fp32 compute).
// ============================================================
__global__ __launch_bounds__(256) void gram_kernel()
{
    const int chunk = blockIdx.x;
    const int bh    = blockIdx.y;
    const int b = bh >> 2, h = bh & 3;

    __shared__ float qs[48][132];
    __shared__ float ks[48][132];

    const __half* qbase = g_dwq + ((size_t)b * C3 + h * HC) * HW;
    const __half* kbase = qbase + (size_t)C_ * HW;

    const int tid = threadIdx.x;
    const int ns = tid & 3;
    const int td = (tid >> 2) & 7;
    const int tc = tid >> 5;

    float acc[6][6];
#pragma unroll
    for (int i = 0; i < 6; i++)
#pragma unroll
        for (int j = 0; j < 6; j++) acc[i][j] = 0.f;
    float nqa[6] = {0,0,0,0,0,0};
    float nka[6] = {0,0,0,0,0,0};

    for (int sub = 0; sub < 4; sub++) {
        const int n0 = (chunk * 4 + sub) * NCHUNK;
        const __half* qb = qbase + n0;
        const __half* kb = kbase + n0;

        __syncthreads();
        for (int i = tid; i < 48 * 16; i += 256) {
            const int r  = i >> 4;
            const int c8 = (i & 15) << 3;
            uint4 vq = *(const uint4*)&qb[(size_t)r * HW + c8];
            uint4 vk = *(const uint4*)&kb[(size_t)r * HW + c8];
            const __half2* hq = (const __half2*)&vq;
            const __half2* hk = (const __half2*)&vk;
#pragma unroll
            for (int j = 0; j < 4; j++) {
                float2 fq = __half22float2(hq[j]);
                float2 fk = __half22float2(hk[j]);
                qs[r][c8 + 2 * j]     = fq.x;
                qs[r][c8 + 2 * j + 1] = fq.y;
                ks[r][c8 + 2 * j]     = fk.x;
                ks[r][c8 + 2 * j + 1] = fk.y;
            }
        }
        __syncthreads();

        for (int nn = 0; nn < 32; nn += 4) {
            const int col = ns * 32 + ((nn + ns * 8) & 31);
            float4 qv[6], kv[6];
#pragma unroll
            for (int i = 0; i < 6; i++) {
                qv[i] = *(float4*)&qs[tc * 6 + i][col];
                kv[i] = *(float4*)&ks[td * 6 + i][col];
            }
#pragma unroll
            for (int i = 0; i < 6; i++)
#pragma unroll
                for (int j = 0; j < 6; j++)
                    acc[i][j] += qv[i].x * kv[j].x + qv[i].y * kv[j].y +
                                 qv[i].z * kv[j].z + qv[i].w * kv[j].w;
            if (td == 0) {
#pragma unroll
                for (int i = 0; i < 6; i++)
                    nqa[i] += qv[i].x * qv[i].x + qv[i].y * qv[i].y +
                              qv[i].z * qv[i].z + qv[i].w * qv[i].w;
            }
            if (tc == 0) {
#pragma unroll
                for (int j = 0; j < 6; j++)
                    nka[j] += kv[j].x * kv[j].x + kv[j].y * kv[j].y +
                              kv[j].z * kv[j].z + kv[j].w * kv[j].w;
            }
        }
    }

    float* out = g_part + ((size_t)(chunk * 4 + ns) * 32 + bh) * PART_STRIDE;
#pragma unroll
    for (int i = 0; i < 6; i++)
#pragma unroll
        for (int j = 0; j < 6; j++)
            out[(tc * 6 + i) * 48 + td * 6 + j] = acc[i][j];
    if (td == 0) {
#pragma unroll
        for (int i = 0; i < 6; i++) out[2304 + tc * 6 + i] = nqa[i];
    }
    if (tc == 0) {
#pragma unroll
        for (int j = 0; j < 6; j++) out[2352 + td * 6 + j] = nka[j];
    }
}

__global__ __launch_bounds__(256) void reduce_kernel()
{
    const int idx = blockIdx.x * 256 + threadIdx.x;
    if (idx >= 32 * PART_STRIDE) return;
    const int bh = idx / PART_STRIDE;
    const int e  = idx % PART_STRIDE;
    const float* p = g_part + (size_t)bh * PART_STRIDE + e;
    float s = 0.f;
    for (int ch = 0; ch < NPART; ch++)
        s += p[(size_t)ch * 32 * PART_STRIDE];
    if (e < 2304)       g_gram[bh * 2304 + e]      = s;
    else if (e < 2352)  g_nq[bh * 48 + (e - 2304)] = s;
    else                g_nk[bh * 48 + (e - 2352)] = s;
}

// ============================================================
__global__ __launch_bounds__(32) void softmax_kernel(const float* __restrict__ temperature)
{
    const int row = blockIdx.x;
    const int bh = row / 48, c = row % 48;
    const int h = bh & 3;
    const int lane = threadIdx.x;

    const float* g = g_gram + (bh * 48 + c) * 48;
    const float t = temperature[h];
    const float qn = fmaxf(sqrtf(g_nq[bh * 48 + c]), 1e-12f);
    const float sq = t / qn;

    float v0 = g[lane] * sq / fmaxf(sqrtf(g_nk[bh * 48 + lane]), 1e-12f);
    float v1 = -3.4e38f;
    if (lane < 16)
        v1 = g[lane + 32] * sq / fmaxf(sqrtf(g_nk[bh * 48 + lane + 32]), 1e-12f);

    float m = fmaxf(v0, v1);
#pragma unroll
    for (int o = 16; o; o >>= 1) m = fmaxf(m, __shfl_xor_sync(0xffffffffu, m, o));
    const float e0 = expf(v0 - m);
    const float e1 = (lane < 16) ? expf(v1 - m) : 0.f;
    float s = e0 + e1;
#pragma unroll
    for (int o = 16; o; o >>= 1) s += __shfl_xor_sync(0xffffffffu, s, o);
    const float inv = 1.f / s;

    float* a = g_attn + (bh * 48 + c) * 48;
    a[lane] = e0 * inv;
    if (lane < 16) a[lane + 32] = e1 * inv;
}

// ============================================================
__global__ __launch_bounds__(256) void weff_kernel(const float* __restrict__ wproj)
{
    const int idx = blockIdx.x * 256 + threadIdx.x;
    if (idx >= B_ * C_ * C_) return;
    const int b = idx / (C_ * C_);
    const int r = idx % (C_ * C_);
    const int o = r / C_;
    const int j = r % C_;
    const int h = j / HC, d = j % HC;

    const float* wp = wproj + o * C_ + h * HC;
    const float* at = g_attn + ((b * 4 + h) * 48) * 48 + d;
    float s = 0.f;
#pragma unroll 8
    for (int cc = 0; cc < 48; cc++)
        s += wp[cc] * at[cc * 48];
    g_weff[idx] = s;
}

// ============================================================
extern "C" void kernel_launch(void* const* d_in, const int* in_sizes, int n_in,
                              void* d_out, int out_size)
{
    const float *x = nullptr, *w_qkv = nullptr, *w_dw = nullptr,
                *temperature = nullptr, *w_proj = nullptr;
    for (int i = 0; i < n_in; i++) {
        switch (in_sizes[i]) {
            case 25165824: x           = (const float*)d_in[i]; break;
            case 110592:   w_qkv       = (const float*)d_in[i]; break;
            case 5184:     w_dw        = (const float*)d_in[i]; break;
            case 4:        temperature = (const float*)d_in[i]; break;
            case 36864:    w_proj      = (const float*)d_in[i]; break;
        }
    }
    float* out = (float*)d_out;

    __half *qkv, *dwq;
    float *weff;
    cudaGetSymbolAddress((void**)&qkv,  g_qkv);
    cudaGetSymbolAddress((void**)&dwq,  g_dwq);
    cudaGetSymbolAddress((void**)&weff, g_weff);

    static bool attr_set = false;
    if (!attr_set) {
        cudaFuncSetAttribute(gemm_f16<false, true>,
                             cudaFuncAttributeMaxDynamicSharedMemorySize, SMEM_G);
        cudaFuncSetAttribute(gemm_f16<true, false>,
                             cudaFuncAttributeMaxDynamicSharedMemorySize, SMEM_G);
        attr_set = true;
    }

    // keep ncu capture slot on the big GEMM
    noop_kernel<<<1, 32>>>();
    noop_kernel<<<1, 32>>>();
    noop_kernel<<<1, 32>>>();

    // 1) qkv[b] = W_qkv @ x[b]  (B fp32, out fp16)
    gemm_f16<false, true><<<dim3(C3 / BM, HW / BN, B_), 128, SMEM_G>>>(
        w_qkv, x, qkv, C_, (size_t)0, (size_t)C_ * HW, (size_t)C3 * HW);

    // 2) depthwise 3x3 (fp16 in/out)
    dwconv_kernel<<<dim3(2, C3, B_), 256>>>(w_dw);

    // 3) Gram + norm partials
    gram_kernel<<<dim3(GCHUNKS, 32), 256>>>();

    // 4) reduce partials
    reduce_kernel<<<(32 * PART_STRIDE + 255) / 256, 256>>>();

    // 5) scaled softmax
    softmax_kernel<<<32 * 48, 32>>>(temperature);

    // 6) Weff = W_proj @ attn
    weff_kernel<<<(B_ * C_ * C_ + 255) / 256, 256>>>(w_proj);

    // 7) out[b] = Weff[b] @ V[b]  (B fp16, out fp32)
    gemm_f16<true, false><<<dim3(C_ / BM, HW / BN, B_), 128, SMEM_G>>>(
        weff, dwq + (size_t)2 * C_ * HW, out, C_,
        (size_t)(C_ * C_), (size_t)C3 * HW, (size_t)C_ * HW);
}

// round 10
// speedup vs baseline: 1.2992x; 1.2992x over previous
#include <cuda_runtime.h>
#include <cuda_fp16.h>
#include <math.h>
#include <stdint.h>

#define B_      8
#define C_      192
#define C3      576
#define HW      16384
#define HEADS_  4
#define HC      48
#define NCHUNK  128
#define GCHUNKS 32
#define NPART   32
#define PART_STRIDE 2400

// -------- device scratch --------
__device__ __half  g_qkv [(size_t)B_ * C3 * HW];
__device__ __half  g_dwq [(size_t)B_ * C3 * HW];
__device__ float   g_part[(size_t)NPART * 32 * PART_STRIDE];
__device__ float   g_gram[32 * HC * HC];
__device__ float   g_nq  [32 * HC];
__device__ float   g_nk  [32 * HC];
__device__ float   g_attn[32 * HC * HC];
// pre-packed fp16 A matrices in fragment layout [mtile][kb 12][k2 8][m 96] half2
__device__ __half2 g_wqkvh[6 * 12 * 8 * 96];          // W_qkv, shared by batches
__device__ __half2 g_weffh[B_ * 2 * 12 * 8 * 96];     // Weff, per batch

// ============================================================
__device__ __forceinline__ void mma_f16(float* d, const uint32_t* a,
                                        uint32_t b0, uint32_t b1) {
    asm volatile(
        "mma.sync.aligned.m16n8k16.row.col.f32.f16.f16.f32 "
        "{%0,%1,%2,%3}, {%4,%5,%6,%7}, {%8,%9}, {%0,%1,%2,%3};\n"
        : "+f"(d[0]), "+f"(d[1]), "+f"(d[2]), "+f"(d[3])
        : "r"(a[0]), "r"(a[1]), "r"(a[2]), "r"(a[3]),
          "r"(b0), "r"(b1));
}

// ============================================================
// Pack W_qkv (576x192 fp32) -> g_wqkvh fragment layout.
// ============================================================
__global__ __launch_bounds__(256) void pack_w_kernel(const float* __restrict__ w)
{
    const int idx = blockIdx.x * 256 + threadIdx.x;   // over 576*96
    if (idx >= C3 * 96) return;
    const int row = idx / 96;
    const int k2  = idx % 96;
    const float v0 = w[row * C_ + 2 * k2];
    const float v1 = w[row * C_ + 2 * k2 + 1];
    g_wqkvh[((row / 96) * 12 + (k2 >> 3)) * 768 + (k2 & 7) * 96 + (row % 96)]
        = __float22half2_rn(make_float2(v0, v1));
}

// ============================================================
// Tensor-core GEMM: C[b] = A_packed(96-row tiles) @ B[b](192xN), N=HW.
// BM=96 BN=128 BK=16. 128 threads / 4 warps (2M x 2N), warp tile 48x64.
// A fragments loaded directly from packed GLOBAL (L1-resident).
// B double-buffered in smem (8.7KB static).
// ============================================================
#define BM 96
#define BN 128
#define BSX 136   // B row stride in half2

template <bool B_HALF, bool OUT_HALF>
__global__ __launch_bounds__(128) void gemm_f16(
    const __half2* __restrict__ Apk, const void* __restrict__ Bv,
    void* __restrict__ Cv, size_t sAb2, size_t sBb, size_t sCb)
{
    __shared__ __half2 Bsh[2][8][BSX];

    const int N = HW;
    const int n0 = blockIdx.y * BN;

    const int tid  = threadIdx.x;
    const int warp = tid >> 5;
    const int lane = tid & 31;
    const int wm = (warp & 1) * 48;
    const int wn = (warp >> 1) * 64;
    const int grp = lane >> 2;
    const int qd  = lane & 3;

    // packed A base for this (batch, mtile)
    const uint32_t* Ap = (const uint32_t*)(Apk + (size_t)blockIdx.z * sAb2 +
                                           (size_t)blockIdx.x * 9216);

    const int bk2 = tid >> 4;            // 0..7
    const int bnc = (tid & 15) << 3;     // 0..120

    const float*  Bf = (const float*)Bv + (size_t)blockIdx.z * sBb;
    const __half* Bh = (const __half*)Bv + (size_t)blockIdx.z * sBb;

    float4 bRegF[4];
    uint4  bRegH[2];

    auto loadG = [&](int k0) {
        if (B_HALF) {
            bRegH[0] = *(const uint4*)&Bh[(size_t)(k0 + 2 * bk2)     * N + n0 + bnc];
            bRegH[1] = *(const uint4*)&Bh[(size_t)(k0 + 2 * bk2 + 1) * N + n0 + bnc];
        } else {
            bRegF[0] = *(const float4*)&Bf[(size_t)(k0 + 2 * bk2)     * N + n0 + bnc];
            bRegF[1] = *(const float4*)&Bf[(size_t)(k0 + 2 * bk2)     * N + n0 + bnc + 4];
            bRegF[2] = *(const float4*)&Bf[(size_t)(k0 + 2 * bk2 + 1) * N + n0 + bnc];
            bRegF[3] = *(const float4*)&Bf[(size_t)(k0 + 2 * bk2 + 1) * N + n0 + bnc + 4];
        }
    };

    auto storeS = [&](int buf) {
        __half2 h[8];
        if (B_HALF) {
            const __half* h0 = (const __half*)&bRegH[0];
            const __half* h1 = (const __half*)&bRegH[1];
#pragma unroll
            for (int j = 0; j < 8; j++) h[j] = __halves2half2(h0[j], h1[j]);
        } else {
            const float r0[8] = {bRegF[0].x, bRegF[0].y, bRegF[0].z, bRegF[0].w,
                                 bRegF[1].x, bRegF[1].y, bRegF[1].z, bRegF[1].w};
            const float r1[8] = {bRegF[2].x, bRegF[2].y, bRegF[2].z, bRegF[2].w,
                                 bRegF[3].x, bRegF[3].y, bRegF[3].z, bRegF[3].w};
#pragma unroll
            for (int j = 0; j < 8; j++) h[j] = __float22half2_rn(make_float2(r0[j], r1[j]));
        }
        *(uint4*)&Bsh[buf][bk2][bnc]     = *(uint4*)&h[0];
        *(uint4*)&Bsh[buf][bk2][bnc + 4] = *(uint4*)&h[4];
    };

    float acc[3][8][4];
#pragma unroll
    for (int i = 0; i < 3; i++)
#pragma unroll
        for (int j = 0; j < 8; j++)
#pragma unroll
            for (int r = 0; r < 4; r++) acc[i][j][r] = 0.f;

    loadG(0);
    storeS(0);
    __syncthreads();

    for (int it = 0; it < 12; it++) {
        const int cur = it & 1;
        if (it + 1 < 12) loadG((it + 1) * 16);

        // A fragments straight from packed global (L1 hits after warmup)
        uint32_t af[3][4];
        const int rA0 = (it * 8 + qd) * 96;
        const int rA1 = (it * 8 + qd + 4) * 96;
#pragma unroll
        for (int mt = 0; mt < 3; mt++) {
            const int m = wm + mt * 16 + grp;
            af[mt][0] = Ap[rA0 + m];
            af[mt][1] = Ap[rA0 + m + 8];
            af[mt][2] = Ap[rA1 + m];
            af[mt][3] = Ap[rA1 + m + 8];
        }
#pragma unroll
        for (int nt = 0; nt < 8; nt++) {
            const int n = wn + nt * 8 + grp;
            const uint32_t b0 = *(const uint32_t*)&Bsh[cur][qd    ][n];
            const uint32_t b1 = *(const uint32_t*)&Bsh[cur][qd + 4][n];
#pragma unroll
            for (int mt = 0; mt < 3; mt++)
                mma_f16(acc[mt][nt], af[mt], b0, b1);
        }

        if (it + 1 < 12) {
            storeS((it + 1) & 1);
            __syncthreads();
        }
    }

    const int m0 = blockIdx.x * BM;
    if (OUT_HALF) {
        __half* Ch = (__half*)Cv + (size_t)blockIdx.z * sCb;
#pragma unroll
        for (int mt = 0; mt < 3; mt++) {
#pragma unroll
            for (int nt = 0; nt < 8; nt++) {
                const int row = m0 + wm + mt * 16 + grp;
                const int col = n0 + wn + nt * 8 + qd * 2;
                *(__half2*)&Ch[(size_t)row * N + col] =
                    __float22half2_rn(make_float2(acc[mt][nt][0], acc[mt][nt][1]));
                *(__half2*)&Ch[(size_t)(row + 8) * N + col] =
                    __float22half2_rn(make_float2(acc[mt][nt][2], acc[mt][nt][3]));
            }
        }
    } else {
        float* Cf = (float*)Cv + (size_t)blockIdx.z * sCb;
#pragma unroll
        for (int mt = 0; mt < 3; mt++) {
#pragma unroll
            for (int nt = 0; nt < 8; nt++) {
                const int row = m0 + wm + mt * 16 + grp;
                const int col = n0 + wn + nt * 8 + qd * 2;
                *(float2*)&Cf[(size_t)row * N + col]       = make_float2(acc[mt][nt][0], acc[mt][nt][1]);
                *(float2*)&Cf[(size_t)(row + 8) * N + col] = make_float2(acc[mt][nt][2], acc[mt][nt][3]);
            }
        }
    }
}

// ============================================================
__global__ void noop_kernel() {}

// ============================================================
// Depthwise 3x3 SAME on fp16 in/out, fp32 compute.
// ============================================================
__global__ __launch_bounds__(256) void dwconv_kernel(const float* __restrict__ wdw)
{
    __shared__ float s[66][130];

    const int half_ = blockIdx.x;
    const int ch    = blockIdx.y;
    const int b     = blockIdx.z;
    const int r0    = half_ * 64;

    const __half* in = g_qkv + ((size_t)b * C3 + ch) * HW;
    __half* outp = g_dwq + ((size_t)b * C3 + ch) * HW;
    const int tid = threadIdx.x;

    for (int r = tid; r < 66; r += 256) { s[r][0] = 0.f; s[r][129] = 0.f; }

    for (int i = tid; i < 66 * 16; i += 256) {
        const int sr = i >> 4;
        const int c8 = (i & 15) << 3;
        const int gr = r0 - 1 + sr;
        if (gr >= 0 && gr < 128) {
            uint4 v = *(const uint4*)&in[gr * 128 + c8];
            const __half2* hp = (const __half2*)&v;
#pragma unroll
            for (int j = 0; j < 4; j++) {
                float2 f = __half22float2(hp[j]);
                s[sr][1 + c8 + 2 * j]     = f.x;
                s[sr][1 + c8 + 2 * j + 1] = f.y;
            }
        } else {
#pragma unroll
            for (int j = 0; j < 8; j++) s[sr][1 + c8 + j] = 0.f;
        }
    }
    __syncthreads();

    float w[9];
#pragma unroll
    for (int i = 0; i < 9; i++) w[i] = __ldg(&wdw[ch * 9 + i]);

    const int lane = tid & 31;
    const int rb   = tid >> 5;

#pragma unroll
    for (int seg = 0; seg < 4; seg++) {
        const int c = lane + seg * 32;
        float o[8];
#pragma unroll
        for (int rr = 0; rr < 10; rr++) {
            const int sr = rb * 8 + rr;
            const float v0 = s[sr][c];
            const float v1 = s[sr][c + 1];
            const float v2 = s[sr][c + 2];
            const float d0 = w[0] * v0 + w[1] * v1 + w[2] * v2;
            const float d1 = w[3] * v0 + w[4] * v1 + w[5] * v2;
            const float d2 = w[6] * v0 + w[7] * v1 + w[8] * v2;
            if (rr < 8)             o[rr]     = d0;
            if (rr >= 1 && rr <= 8) o[rr - 1] += d1;
            if (rr >= 2)            o[rr - 2] += d2;
        }
#pragma unroll
        for (int y = 0; y < 8; y++)
            outp[(r0 + rb * 8 + y) * 128 + c] = __float2half_rn(o[y]);
    }
}

// ============================================================
// Partial Gram (48x48) + q/k norm partials. ns-split reduced in-warp
// via shfl (deterministic), one partial slot per chunk (NPART=32).
// ============================================================
__global__ __launch_bounds__(256) void gram_kernel()
{
    const int chunk = blockIdx.x;
    const int bh    = blockIdx.y;
    const int b = bh >> 2, h = bh & 3;

    __shared__ float qs[48][132];
    __shared__ float ks[48][132];

    const __half* qbase = g_dwq + ((size_t)b * C3 + h * HC) * HW;
    const __half* kbase = qbase + (size_t)C_ * HW;

    const int tid = threadIdx.x;
    const int ns = tid & 3;
    const int td = (tid >> 2) & 7;
    const int tc = tid >> 5;

    float acc[6][6];
#pragma unroll
    for (int i = 0; i < 6; i++)
#pragma unroll
        for (int j = 0; j < 6; j++) acc[i][j] = 0.f;
    float nqa[6] = {0,0,0,0,0,0};
    float nka[6] = {0,0,0,0,0,0};

    for (int sub = 0; sub < 4; sub++) {
        const int n0 = (chunk * 4 + sub) * NCHUNK;
        const __half* qb = qbase + n0;
        const __half* kb = kbase + n0;

        __syncthreads();
        for (int i = tid; i < 48 * 16; i += 256) {
            const int r  = i >> 4;
            const int c8 = (i & 15) << 3;
            uint4 vq = *(const uint4*)&qb[(size_t)r * HW + c8];
            uint4 vk = *(const uint4*)&kb[(size_t)r * HW + c8];
            const __half2* hq = (const __half2*)&vq;
            const __half2* hk = (const __half2*)&vk;
#pragma unroll
            for (int j = 0; j < 4; j++) {
                float2 fq = __half22float2(hq[j]);
                float2 fk = __half22float2(hk[j]);
                qs[r][c8 + 2 * j]     = fq.x;
                qs[r][c8 + 2 * j + 1] = fq.y;
                ks[r][c8 + 2 * j]     = fk.x;
                ks[r][c8 + 2 * j + 1] = fk.y;
            }
        }
        __syncthreads();

        for (int nn = 0; nn < 32; nn += 4) {
            const int col = ns * 32 + ((nn + ns * 8) & 31);
            float4 qv[6], kv[6];
#pragma unroll
            for (int i = 0; i < 6; i++) {
                qv[i] = *(float4*)&qs[tc * 6 + i][col];
                kv[i] = *(float4*)&ks[td * 6 + i][col];
            }
#pragma unroll
            for (int i = 0; i < 6; i++)
#pragma unroll
                for (int j = 0; j < 6; j++)
                    acc[i][j] += qv[i].x * kv[j].x + qv[i].y * kv[j].y +
                                 qv[i].z * kv[j].z + qv[i].w * kv[j].w;
            if (td == 0) {
#pragma unroll
                for (int i = 0; i < 6; i++)
                    nqa[i] += qv[i].x * qv[i].x + qv[i].y * qv[i].y +
                              qv[i].z * qv[i].z + qv[i].w * qv[i].w;
            }
            if (tc == 0) {
#pragma unroll
                for (int j = 0; j < 6; j++)
                    nka[j] += kv[j].x * kv[j].x + kv[j].y * kv[j].y +
                              kv[j].z * kv[j].z + kv[j].w * kv[j].w;
            }
        }
    }

    // in-warp reduction over ns (lanes differ in bits 0-1) — deterministic
#pragma unroll
    for (int i = 0; i < 6; i++)
#pragma unroll
        for (int j = 0; j < 6; j++) {
            float v = acc[i][j];
            v += __shfl_xor_sync(0xffffffffu, v, 1);
            v += __shfl_xor_sync(0xffffffffu, v, 2);
            acc[i][j] = v;
        }
#pragma unroll
    for (int i = 0; i < 6; i++) {
        float v = nqa[i];
        v += __shfl_xor_sync(0xffffffffu, v, 1);
        v += __shfl_xor_sync(0xffffffffu, v, 2);
        nqa[i] = v;
        float u = nka[i];
        u += __shfl_xor_sync(0xffffffffu, u, 1);
        u += __shfl_xor_sync(0xffffffffu, u, 2);
        nka[i] = u;
    }

    if (ns == 0) {
        float* out = g_part + ((size_t)chunk * 32 + bh) * PART_STRIDE;
#pragma unroll
        for (int i = 0; i < 6; i++)
#pragma unroll
            for (int j = 0; j < 6; j++)
                out[(tc * 6 + i) * 48 + td * 6 + j] = acc[i][j];
        if (td == 0) {
#pragma unroll
            for (int i = 0; i < 6; i++) out[2304 + tc * 6 + i] = nqa[i];
        }
        if (tc == 0) {
#pragma unroll
            for (int j = 0; j < 6; j++) out[2352 + td * 6 + j] = nka[j];
        }
    }
}

__global__ __launch_bounds__(256) void reduce_kernel()
{
    const int idx = blockIdx.x * 256 + threadIdx.x;
    if (idx >= 32 * PART_STRIDE) return;
    const int bh = idx / PART_STRIDE;
    const int e  = idx % PART_STRIDE;
    const float* p = g_part + (size_t)bh * PART_STRIDE + e;
    float s = 0.f;
    for (int ch = 0; ch < NPART; ch++)
        s += p[(size_t)ch * 32 * PART_STRIDE];
    if (e < 2304)       g_gram[bh * 2304 + e]      = s;
    else if (e < 2352)  g_nq[bh * 48 + (e - 2304)] = s;
    else                g_nk[bh * 48 + (e - 2352)] = s;
}

// ============================================================
__global__ __launch_bounds__(32) void softmax_kernel(const float* __restrict__ temperature)
{
    const int row = blockIdx.x;
    const int bh = row / 48, c = row % 48;
    const int h = bh & 3;
    const int lane = threadIdx.x;

    const float* g = g_gram + (bh * 48 + c) * 48;
    const float t = temperature[h];
    const float qn = fmaxf(sqrtf(g_nq[bh * 48 + c]), 1e-12f);
    const float sq = t / qn;

    float v0 = g[lane] * sq / fmaxf(sqrtf(g_nk[bh * 48 + lane]), 1e-12f);
    float v1 = -3.4e38f;
    if (lane < 16)
        v1 = g[lane + 32] * sq / fmaxf(sqrtf(g_nk[bh * 48 + lane + 32]), 1e-12f);

    float m = fmaxf(v0, v1);
#pragma unroll
    for (int o = 16; o; o >>= 1) m = fmaxf(m, __shfl_xor_sync(0xffffffffu, m, o));
    const float e0 = expf(v0 - m);
    const float e1 = (lane < 16) ? expf(v1 - m) : 0.f;
    float s = e0 + e1;
#pragma unroll
    for (int o = 16; o; o >>= 1) s += __shfl_xor_sync(0xffffffffu, s, o);
    const float inv = 1.f / s;

    float* a = g_attn + (bh * 48 + c) * 48;
    a[lane] = e0 * inv;
    if (lane < 16) a[lane + 32] = e1 * inv;
}

// ============================================================
// Weff[b][o][j] = sum_cc wproj[o][h*48+cc] * attn[b,h,cc,d], j=h*48+d.
// Written DIRECTLY in packed fp16 fragment layout for gemm2's A.
// ============================================================
__global__ __launch_bounds__(256) void weff_kernel(const float* __restrict__ wproj)
{
    const int idx = blockIdx.x * 256 + threadIdx.x;
    if (idx >= B_ * C_ * C_) return;
    const int b = idx / (C_ * C_);
    const int r = idx % (C_ * C_);
    const int o = r / C_;
    const int j = r % C_;
    const int h = j / HC, d = j % HC;

    const float* wp = wproj + o * C_ + h * HC;
    const float* at = g_attn + ((b * 4 + h) * 48) * 48 + d;
    float s = 0.f;
#pragma unroll 8
    for (int cc = 0; cc < 48; cc++)
        s += wp[cc] * at[cc * 48];

    // packed write: [b][mtile=o/96][kb=j/16][k2=(j>>1)&7][m=o%96], half (j&1)
    const size_t idx2 = ((size_t)(b * 2 + o / 96) * 12 + (j >> 4)) * 768 +
                        ((j >> 1) & 7) * 96 + (o % 96);
    ((__half*)g_weffh)[idx2 * 2 + (j & 1)] = __float2half_rn(s);
}

// ============================================================
extern "C" void kernel_launch(void* const* d_in, const int* in_sizes, int n_in,
                              void* d_out, int out_size)
{
    const float *x = nullptr, *w_qkv = nullptr, *w_dw = nullptr,
                *temperature = nullptr, *w_proj = nullptr;
    for (int i = 0; i < n_in; i++) {
        switch (in_sizes[i]) {
            case 25165824: x           = (const float*)d_in[i]; break;
            case 110592:   w_qkv       = (const float*)d_in[i]; break;
            case 5184:     w_dw        = (const float*)d_in[i]; break;
            case 4:        temperature = (const float*)d_in[i]; break;
            case 36864:    w_proj      = (const float*)d_in[i]; break;
        }
    }
    float* out = (float*)d_out;

    __half *qkv, *dwq;
    __half2 *wqkvh, *weffh;
    cudaGetSymbolAddress((void**)&qkv,   g_qkv);
    cudaGetSymbolAddress((void**)&dwq,   g_dwq);
    cudaGetSymbolAddress((void**)&wqkvh, g_wqkvh);
    cudaGetSymbolAddress((void**)&weffh, g_weffh);

    // keep ncu capture slot (4th launch) on the big GEMM
    noop_kernel<<<1, 32>>>();
    noop_kernel<<<1, 32>>>();

    // 0) pack W_qkv -> fp16 fragment layout
    pack_w_kernel<<<(C3 * 96 + 255) / 256, 256>>>(w_qkv);

    // 1) qkv[b] = W_qkv @ x[b]  (A packed global, B fp32, out fp16)
    gemm_f16<false, true><<<dim3(C3 / BM, HW / BN, B_), 128>>>(
        wqkvh, x, qkv, (size_t)0, (size_t)C_ * HW, (size_t)C3 * HW);

    // 2) depthwise 3x3 (fp16 in/out)
    dwconv_kernel<<<dim3(2, C3, B_), 256>>>(w_dw);

    // 3) Gram + norm partials (in-warp ns reduction, NPART=32)
    gram_kernel<<<dim3(GCHUNKS, 32), 256>>>();

    // 4) reduce partials
    reduce_kernel<<<(32 * PART_STRIDE + 255) / 256, 256>>>();

    // 5) scaled softmax
    softmax_kernel<<<32 * 48, 32>>>(temperature);

    // 6) Weff = W_proj @ attn, written packed fp16
    weff_kernel<<<(B_ * C_ * C_ + 255) / 256, 256>>>(w_proj);

    // 7) out[b] = Weff[b] @ V[b]  (A packed global per batch, B fp16, out fp32)
    gemm_f16<true, false><<<dim3(C_ / BM, HW / BN, B_), 128>>>(
        weffh, dwq + (size_t)2 * C_ * HW, out,
        (size_t)(2 * 9216), (size_t)C3 * HW, (size_t)C_ * HW);
}